// round 9
// baseline (speedup 1.0000x reference)
#include <cuda_runtime.h>
#include <cuda_bf16.h>
#include <math.h>
#include <stdint.h>

#define N_ENT_MAX 150016
#define H 128
#define DEG 32
#define TOPK 10
#define TILE_M 64
#define K_PAD 136     // bf16 elems per smem row (272B) -> conflict-free ldmatrix
#define D_PAD 132     // f32 elems per D smem row

// -------- device scratch (no allocs allowed) --------
__device__ float g_h_node[N_ENT_MAX * H];
__device__ float g_neigh[N_ENT_MAX * H];
__device__ float g_s_src[N_ENT_MAX];
__device__ float g_s_dst[N_ENT_MAX];
__device__ float g_h_rel[512 * H];
__device__ float g_s_rel[512];
// Pre-transposed B operands: B[n][k] = Wmat[k][n], bf16 hi/lo, rows padded to K_PAD
__device__ __align__(16) __nv_bfloat16 g_BW_hi[H * K_PAD];
__device__ __align__(16) __nv_bfloat16 g_BW_lo[H * K_PAD];
__device__ __align__(16) __nv_bfloat16 g_BN_hi[H * K_PAD];
__device__ __align__(16) __nv_bfloat16 g_BN_lo[H * K_PAD];

// ---------------- helpers ---------------------------
__device__ __forceinline__ uint32_t smem_u32(const void* p) {
    uint32_t a;
    asm("{ .reg .u64 t; cvta.to.shared.u64 t, %1; cvt.u32.u64 %0, t; }"
        : "=r"(a) : "l"(p));
    return a;
}

#define LDMX4(r0, r1, r2, r3, addr)                                             \
    asm volatile("ldmatrix.sync.aligned.m8n8.x4.shared.b16 {%0,%1,%2,%3}, [%4];"\
                 : "=r"(r0), "=r"(r1), "=r"(r2), "=r"(r3) : "r"(addr))

__device__ __forceinline__ void mma16816(float* c, uint32_t a0, uint32_t a1,
                                         uint32_t a2, uint32_t a3,
                                         uint32_t b0, uint32_t b1) {
    asm volatile(
        "mma.sync.aligned.m16n8k16.row.col.f32.bf16.bf16.f32 "
        "{%0,%1,%2,%3}, {%4,%5,%6,%7}, {%8,%9}, {%0,%1,%2,%3};"
        : "+f"(c[0]), "+f"(c[1]), "+f"(c[2]), "+f"(c[3])
        : "r"(a0), "r"(a1), "r"(a2), "r"(a3), "r"(b0), "r"(b1));
}

// ============ prep: B[n][k] = src[k][n] as bf16 hi/lo ======================
__global__ void kprepB(const float* __restrict__ W, const float* __restrict__ NW) {
    int tid = blockIdx.x * blockDim.x + threadIdx.x;
    if (tid >= H * H) return;
    int k = tid >> 7, nn = tid & 127;
    int off = nn * K_PAD + k;
    {
        float f = W[tid];
        __nv_bfloat16 hi = __float2bfloat16_rn(f);
        g_BW_hi[off] = hi;
        g_BW_lo[off] = __float2bfloat16_rn(f - __bfloat162float(hi));
    }
    {
        float f = NW[tid];
        __nv_bfloat16 hi = __float2bfloat16_rn(f);
        g_BN_hi[off] = hi;
        g_BN_lo[off] = __float2bfloat16_rn(f - __bfloat162float(hi));
    }
}

// ===================== kernel A: h_rel + s_rel (tiny) ======================
__global__ void krel(const float* __restrict__ rel_emb,
                     const float* __restrict__ W_r,
                     const float* __restrict__ a) {
    int r = blockIdx.x;
    int j = threadIdx.x;                 // 128 threads
    const float* x = rel_emb + r * H;
    float acc = 0.f;
#pragma unroll 8
    for (int h = 0; h < H; ++h) acc = fmaf(x[h], W_r[h * H + j], acc);
    g_h_rel[r * H + j] = acc;
    __shared__ float red[H];
    red[j] = acc * a[2 * H + j];
    __syncthreads();
    for (int off = 64; off > 0; off >>= 1) {
        if (j < off) red[j] += red[j + off];
        __syncthreads();
    }
    if (j == 0) g_s_rel[r] = red[0];
}

// ====== persistent warp-MMA GEMM: Y = X @ Wmat (+ epilogue), 4 passes =====
// MODE 0: X=ent_emb, writes g_h_node + s_src/s_dst  (B = g_BW)
// MODE 1: X=g_neigh, writes out = tanh(.)           (B = g_BN)
// SMEM: Bhi@0 (34816), Blo@34816, Ahi@69632 (17408), Alo@87040 (17408),
//       a1@104448, a2@104960; D (f32 64x132 = 33792) reuses @69632.
#define SM_BHI 0
#define SM_BLO 34816
#define SM_A   69632
#define SM_ALO 87040
#define SM_A1  104448
#define SM_A2  104960
#define SM_TOTAL 105472
#define GRID_GEMM 296   // 2 blocks/SM x 148 SMs

template <int MODE>
__global__ void __launch_bounds__(256) kgemm(const float* __restrict__ Xin,
                                             const float* __restrict__ avec,
                                             float* __restrict__ out,
                                             int n, int ntiles) {
    extern __shared__ char sm[];
    uint32_t sb = smem_u32(sm);
    float* a1s = (float*)(sm + SM_A1);
    float* a2s = (float*)(sm + SM_A2);
    float* D = (float*)(sm + SM_A);      // reuses A region after MMA
    __nv_bfloat16* Ahi = (__nv_bfloat16*)(sm + SM_A);
    __nv_bfloat16* Alo = (__nv_bfloat16*)(sm + SM_ALO);
    int tid = threadIdx.x;
    int w = tid >> 5, l = tid & 31;
    int wm = w >> 2, wn = w & 3;         // warp grid 2 (M) x 4 (N)
    int quad = l >> 3, lrow = l & 7;

    if (MODE == 0 && tid < 128) { a1s[tid] = avec[tid]; a2s[tid] = avec[H + tid]; }

    // ---- stage B ONCE per persistent block (hi+lo, 2x34816B) ----
    {
        const uint4* bh = (const uint4*)(MODE == 0 ? (const void*)g_BW_hi : (const void*)g_BN_hi);
        const uint4* bl = (const uint4*)(MODE == 0 ? (const void*)g_BW_lo : (const void*)g_BN_lo);
        uint4* dh = (uint4*)(sm + SM_BHI);
        uint4* dl = (uint4*)(sm + SM_BLO);
        for (int i = tid; i < (H * K_PAD * 2) / 16; i += 256) { dh[i] = bh[i]; dl[i] = bl[i]; }
    }

    const float* X = (MODE == 0) ? Xin : g_neigh;
    const float4* X4 = (const float4*)X;

    // per-lane ldmatrix byte offsets within a tile
    uint32_t a_loff = (uint32_t)(((lrow + (quad & 1) * 8) * K_PAD + (quad >> 1) * 8) * 2);
    uint32_t b_loff = (uint32_t)(((lrow + (quad >> 1) * 8) * K_PAD + (quad & 1) * 8) * 2);

    for (int t = blockIdx.x; t < ntiles; t += GRID_GEMM) {
        int row0 = t * TILE_M;
        __syncthreads();                 // prev-iter D reads done / B ready

        // ---- stage A: 64 rows fp32 -> bf16 hi/lo ----
#pragma unroll
        for (int it = 0; it < 8; ++it) {
            int idx = it * 256 + tid;        // 2048 float4s
            int r = idx >> 5, s = idx & 31;
            int row = row0 + r;
            float4 v = make_float4(0.f, 0.f, 0.f, 0.f);
            if (row < n) v = X4[(size_t)row * 32 + s];
            __nv_bfloat16 h0 = __float2bfloat16_rn(v.x);
            __nv_bfloat16 h1 = __float2bfloat16_rn(v.y);
            __nv_bfloat16 h2 = __float2bfloat16_rn(v.z);
            __nv_bfloat16 h3 = __float2bfloat16_rn(v.w);
            __nv_bfloat162 ph0 = __halves2bfloat162(h0, h1);
            __nv_bfloat162 ph1 = __halves2bfloat162(h2, h3);
            uint2 uh; uh.x = *(uint32_t*)&ph0; uh.y = *(uint32_t*)&ph1;
            *(uint2*)(Ahi + r * K_PAD + 4 * s) = uh;
            __nv_bfloat162 pl0 = __halves2bfloat162(
                __float2bfloat16_rn(v.x - __bfloat162float(h0)),
                __float2bfloat16_rn(v.y - __bfloat162float(h1)));
            __nv_bfloat162 pl1 = __halves2bfloat162(
                __float2bfloat16_rn(v.z - __bfloat162float(h2)),
                __float2bfloat16_rn(v.w - __bfloat162float(h3)));
            uint2 ul; ul.x = *(uint32_t*)&pl0; ul.y = *(uint32_t*)&pl1;
            *(uint2*)(Alo + r * K_PAD + 4 * s) = ul;
        }
        __syncthreads();

        // ---- 4-pass warp MMA: AhBh + AhBl + AlBh + AlBl ----
        float acc[2][4][4];              // [m16-tile][n8-tile][frag]
#pragma unroll
        for (int i = 0; i < 2; i++)
#pragma unroll
            for (int j = 0; j < 4; j++)
#pragma unroll
                for (int q = 0; q < 4; q++) acc[i][j][q] = 0.f;

#pragma unroll
        for (int pass = 0; pass < 4; pass++) {
            uint32_t abase = sb + ((pass & 2) ? SM_ALO : SM_A);
            uint32_t bbase = sb + ((pass & 1) ? SM_BLO : SM_BHI);
            uint32_t arow = abase + (uint32_t)(wm * 32) * (K_PAD * 2) + a_loff;
            uint32_t brow = bbase + (uint32_t)(wn * 32) * (K_PAD * 2) + b_loff;
#pragma unroll
            for (int ks = 0; ks < 8; ks++) {
                uint32_t k0 = ks * 32;   // 16 bf16 = 32 bytes
                uint32_t af[2][4], bf[2][4];
#pragma unroll
                for (int mt = 0; mt < 2; mt++)
                    LDMX4(af[mt][0], af[mt][1], af[mt][2], af[mt][3],
                          arow + (uint32_t)(mt * 16) * (K_PAD * 2) + k0);
#pragma unroll
                for (int nt = 0; nt < 2; nt++)
                    LDMX4(bf[nt][0], bf[nt][1], bf[nt][2], bf[nt][3],
                          brow + (uint32_t)(nt * 16) * (K_PAD * 2) + k0);
#pragma unroll
                for (int mt = 0; mt < 2; mt++)
#pragma unroll
                    for (int q = 0; q < 4; q++)
                        mma16816(acc[mt][q], af[mt][0], af[mt][1], af[mt][2], af[mt][3],
                                 bf[q >> 1][(q & 1) * 2], bf[q >> 1][(q & 1) * 2 + 1]);
            }
        }
        __syncthreads();                 // all ldmatrix reads done before D overwrite

        // ---- frags -> D smem (row pad 132) ----
#pragma unroll
        for (int mt = 0; mt < 2; mt++) {
            int row = wm * 32 + mt * 16 + (l >> 2);
#pragma unroll
            for (int q = 0; q < 4; q++) {
                int col = wn * 32 + q * 8 + 2 * (l & 3);
                *(float2*)(D + row * D_PAD + col) = make_float2(acc[mt][q][0], acc[mt][q][1]);
                *(float2*)(D + (row + 8) * D_PAD + col) = make_float2(acc[mt][q][2], acc[mt][q][3]);
            }
        }
        __syncthreads();

        // ---- epilogue ----
        if (MODE == 0) {
#pragma unroll
            for (int it = 0; it < 8; ++it) {
                int idx = it * 256 + tid;    // 2048 float4s
                int r = idx >> 5, s = idx & 31;
                int row = row0 + r;
                if (row < n) {
                    float4 v = *(float4*)(D + r * D_PAD + 4 * s);
                    *(float4*)(g_h_node + (size_t)row * H + 4 * s) = v;
                }
            }
            if (tid < 128) {
                int r = tid & 63;
                int row = row0 + r;
                if (row < n) {
                    const float* av = (tid < 64) ? a1s : a2s;
                    float p = 0.f;
                    const float* dr = D + r * D_PAD;
#pragma unroll 8
                    for (int c = 0; c < H; c++) p = fmaf(dr[c], av[c], p);
                    if (tid < 64) g_s_src[row] = p; else g_s_dst[row] = p;
                }
            }
        } else {
#pragma unroll
            for (int it = 0; it < 8; ++it) {
                int idx = it * 256 + tid;
                int r = idx >> 5, s = idx & 31;
                int row = row0 + r;
                if (row < n) {
                    float4 v = *(float4*)(D + r * D_PAD + 4 * s);
                    *(float4*)(out + (size_t)row * H + 4 * s) =
                        make_float4(tanhf(v.x), tanhf(v.y), tanhf(v.z), tanhf(v.w));
                }
            }
        }
    }
}

// ====== kgather: score -> top10 -> softmax -> gather-agg -> g_neigh =======
#define G_WARPS 8
__global__ void __launch_bounds__(256) kgather(const int* __restrict__ src,
                                               const int* __restrict__ rid, int n) {
    __shared__ float ats[G_WARPS][16];
    __shared__ int   sks[G_WARPS][16];
    __shared__ int   rks[G_WARPS][16];
    int tid = threadIdx.x;
    int w = tid >> 5, l = tid & 31;
    int node = blockIdx.x * G_WARPS + w;
    if (node >= n) return;

    float sdst = g_s_dst[node];
    int s = src[node * DEG + l];
    int r = rid[node * DEG + l];
    float v = (g_s_src[s] + sdst) + g_s_rel[r];
    float sc = (v >= 0.f) ? v : 0.2f * v;

    int rank = 0;
#pragma unroll
    for (int j = 0; j < DEG; j++) {
        float vj = __shfl_sync(0xffffffffu, sc, j);
        rank += (vj > sc) || (vj == sc && j < l);
    }
    bool sel = (rank < TOPK);

    float m = sel ? sc : __int_as_float(0xff800000);
#pragma unroll
    for (int off = 16; off; off >>= 1) m = fmaxf(m, __shfl_xor_sync(0xffffffffu, m, off));
    float e = sel ? expf(sc - m) : 0.f;
    float z = e;
#pragma unroll
    for (int off = 16; off; off >>= 1) z += __shfl_xor_sync(0xffffffffu, z, off);
    float attn = e / z;

    if (sel) { ats[w][rank] = attn; sks[w][rank] = s; rks[w][rank] = r; }
    __syncwarp();

    float4 acc = make_float4(0.f, 0.f, 0.f, 0.f);
#pragma unroll
    for (int k = 0; k < TOPK; k++) {
        int sk = sks[w][k], rk = rks[w][k];
        float ak = ats[w][k];
        float4 hn = *(const float4*)(g_h_node + (size_t)sk * H + 4 * l);
        float4 hr = *(const float4*)(g_h_rel + rk * H + 4 * l);
        acc.x = fmaf(ak, hn.x + hr.x, acc.x);
        acc.y = fmaf(ak, hn.y + hr.y, acc.y);
        acc.z = fmaf(ak, hn.z + hr.z, acc.z);
        acc.w = fmaf(ak, hn.w + hr.w, acc.w);
    }
    *(float4*)(g_neigh + (size_t)node * H + 4 * l) = acc;
}

// ============================== launch =====================================
extern "C" void kernel_launch(void* const* d_in, const int* in_sizes, int n_in,
                              void* d_out, int out_size) {
    const float* ent = (const float*)d_in[0];
    const float* rel = (const float*)d_in[1];
    const float* W   = (const float*)d_in[2];
    const float* W_r = (const float*)d_in[3];
    const float* a   = (const float*)d_in[4];
    const float* nw  = (const float*)d_in[5];
    const int*   src = (const int*)d_in[6];
    const int*   rid = (const int*)d_in[7];
    float* out = (float*)d_out;

    int n    = in_sizes[0] / H;   // 150000
    int nrel = in_sizes[1] / H;   // 500
    int ntiles = (n + TILE_M - 1) / TILE_M;

    cudaFuncSetAttribute(kgemm<0>, cudaFuncAttributeMaxDynamicSharedMemorySize, SM_TOTAL);
    cudaFuncSetAttribute(kgemm<1>, cudaFuncAttributeMaxDynamicSharedMemorySize, SM_TOTAL);

    kprepB<<<(H * H + 255) / 256, 256>>>(W, nw);
    krel<<<nrel, H>>>(rel, W_r, a);
    kgemm<0><<<GRID_GEMM, 256, SM_TOTAL>>>(ent, a, nullptr, n, ntiles);
    kgather<<<(n + G_WARPS - 1) / G_WARPS, 256>>>(src, rid, n);
    kgemm<1><<<GRID_GEMM, 256, SM_TOTAL>>>(nullptr, a, out, n, ntiles);
}

// round 10
// speedup vs baseline: 1.1336x; 1.1336x over previous
#include <cuda_runtime.h>
#include <cuda_bf16.h>
#include <math.h>
#include <stdint.h>

#define N_ENT_MAX 150016
#define H 128
#define DEG 32
#define TOPK 10
#define TILE_M 64
#define K_PAD 136     // bf16 elems per smem row (272B) -> conflict-free ldmatrix
#define D_PAD 132     // f32 elems per D smem row

// -------- device scratch (no allocs allowed) --------
__device__ float g_h_node[N_ENT_MAX * H];
__device__ float g_neigh[N_ENT_MAX * H];
__device__ float g_s_src[N_ENT_MAX];
__device__ float g_s_dst[N_ENT_MAX];
__device__ float g_h_rel[512 * H];
__device__ float g_s_rel[512];
// Pre-transposed B operands: B[n][k] = Wmat[k][n], bf16 hi/lo, rows padded to K_PAD
__device__ __align__(16) __nv_bfloat16 g_BW_hi[H * K_PAD];
__device__ __align__(16) __nv_bfloat16 g_BW_lo[H * K_PAD];
__device__ __align__(16) __nv_bfloat16 g_BN_hi[H * K_PAD];
__device__ __align__(16) __nv_bfloat16 g_BN_lo[H * K_PAD];

// ---------------- helpers ---------------------------
__device__ __forceinline__ uint32_t smem_u32(const void* p) {
    uint32_t a;
    asm("{ .reg .u64 t; cvta.to.shared.u64 t, %1; cvt.u32.u64 %0, t; }"
        : "=r"(a) : "l"(p));
    return a;
}

#define LDMX4(r0, r1, r2, r3, addr)                                             \
    asm volatile("ldmatrix.sync.aligned.m8n8.x4.shared.b16 {%0,%1,%2,%3}, [%4];"\
                 : "=r"(r0), "=r"(r1), "=r"(r2), "=r"(r3) : "r"(addr))

__device__ __forceinline__ void mma16816(float* c, uint32_t a0, uint32_t a1,
                                         uint32_t a2, uint32_t a3,
                                         uint32_t b0, uint32_t b1) {
    asm volatile(
        "mma.sync.aligned.m16n8k16.row.col.f32.bf16.bf16.f32 "
        "{%0,%1,%2,%3}, {%4,%5,%6,%7}, {%8,%9}, {%0,%1,%2,%3};"
        : "+f"(c[0]), "+f"(c[1]), "+f"(c[2]), "+f"(c[3])
        : "r"(a0), "r"(a1), "r"(a2), "r"(a3), "r"(b0), "r"(b1));
}

// ============ prep: B[n][k] = src[k][n] as bf16 hi/lo ======================
__global__ void kprepB(const float* __restrict__ W, const float* __restrict__ NW) {
    int tid = blockIdx.x * blockDim.x + threadIdx.x;
    if (tid >= H * H) return;
    int k = tid >> 7, nn = tid & 127;
    int off = nn * K_PAD + k;
    {
        float f = W[tid];
        __nv_bfloat16 hi = __float2bfloat16_rn(f);
        g_BW_hi[off] = hi;
        g_BW_lo[off] = __float2bfloat16_rn(f - __bfloat162float(hi));
    }
    {
        float f = NW[tid];
        __nv_bfloat16 hi = __float2bfloat16_rn(f);
        g_BN_hi[off] = hi;
        g_BN_lo[off] = __float2bfloat16_rn(f - __bfloat162float(hi));
    }
}

// ====== persistent warp-MMA GEMM: Y = X @ Wmat (+ epilogue), 3 passes =====
// MODE 0: X=ent_emb, writes g_h_node + s_src/s_dst (B = g_BW); also computes
//         h_rel/s_rel in its prologue (2 relations per block, blocks 0-249).
// MODE 1: X=g_neigh, writes out = tanh(.)          (B = g_BN)
// SMEM: Bhi@0 (34816), Blo@34816, Ahi@69632 (17408), Alo@87040 (17408),
//       a1@104448, a2@104960; D (f32 64x132 = 33792) reuses @69632.
#define SM_BHI 0
#define SM_BLO 34816
#define SM_A   69632
#define SM_ALO 87040
#define SM_A1  104448
#define SM_A2  104960
#define SM_TOTAL 105472
#define GRID_GEMM 296   // 2 blocks/SM x 148 SMs

template <int MODE>
__global__ void __launch_bounds__(256) kgemm(const float* __restrict__ Xin,
                                             const float* __restrict__ avec,
                                             const float* __restrict__ rel_emb,
                                             const float* __restrict__ W_r,
                                             float* __restrict__ out,
                                             int n, int ntiles, int nrel) {
    extern __shared__ char sm[];
    uint32_t sb = smem_u32(sm);
    float* a1s = (float*)(sm + SM_A1);
    float* a2s = (float*)(sm + SM_A2);
    float* D = (float*)(sm + SM_A);      // reuses A region after MMA
    __nv_bfloat16* Ahi = (__nv_bfloat16*)(sm + SM_A);
    __nv_bfloat16* Alo = (__nv_bfloat16*)(sm + SM_ALO);
    int tid = threadIdx.x;
    int w = tid >> 5, l = tid & 31;
    int wm = w >> 2, wn = w & 3;         // warp grid 2 (M) x 4 (N)
    int quad = l >> 3, lrow = l & 7;

    if (MODE == 0 && tid < 128) { a1s[tid] = avec[tid]; a2s[tid] = avec[H + tid]; }

    // ---- inline krel: blocks 0..(nrel+1)/2-1 handle 2 relations each ----
    if (MODE == 0 && blockIdx.x < (nrel + 1) / 2) {
        int rr = blockIdx.x * 2 + (tid >> 7);
        int j = tid & 127;
        if (rr < nrel) {
            const float* x = rel_emb + rr * H;
            float acc = 0.f;
#pragma unroll 8
            for (int h = 0; h < H; ++h) acc = fmaf(x[h], W_r[h * H + j], acc);
            g_h_rel[rr * H + j] = acc;
            float p = acc * avec[2 * H + j];
#pragma unroll
            for (int off = 16; off; off >>= 1) p += __shfl_xor_sync(0xffffffffu, p, off);
            if ((tid & 31) == 0) D[tid >> 5] = p;
        }
        __syncthreads();
        if ((tid & 127) == 0 && rr < nrel) {
            int b = (tid >> 7) * 4;
            g_s_rel[rr] = D[b] + D[b + 1] + D[b + 2] + D[b + 3];
        }
    }

    // ---- stage B ONCE per persistent block (hi+lo, 2x34816B) ----
    {
        const uint4* bh = (const uint4*)(MODE == 0 ? (const void*)g_BW_hi : (const void*)g_BN_hi);
        const uint4* bl = (const uint4*)(MODE == 0 ? (const void*)g_BW_lo : (const void*)g_BN_lo);
        uint4* dh = (uint4*)(sm + SM_BHI);
        uint4* dl = (uint4*)(sm + SM_BLO);
        for (int i = tid; i < (H * K_PAD * 2) / 16; i += 256) { dh[i] = bh[i]; dl[i] = bl[i]; }
    }

    const float* X = (MODE == 0) ? Xin : g_neigh;
    const float4* X4 = (const float4*)X;

    // per-lane ldmatrix byte offsets within a tile
    uint32_t a_loff = (uint32_t)(((lrow + (quad & 1) * 8) * K_PAD + (quad >> 1) * 8) * 2);
    uint32_t b_loff = (uint32_t)(((lrow + (quad >> 1) * 8) * K_PAD + (quad & 1) * 8) * 2);

    // software pipeline: gmem A-tile prefetched into regs one iter ahead
    float4 pre[8];
    {
        int t0 = blockIdx.x;
        int row0 = t0 * TILE_M;
#pragma unroll
        for (int it = 0; it < 8; ++it) {
            int idx = it * 256 + tid;
            int r = idx >> 5, s = idx & 31;
            int row = row0 + r;
            pre[it] = make_float4(0.f, 0.f, 0.f, 0.f);
            if (t0 < ntiles && row < n) pre[it] = X4[(size_t)row * 32 + s];
        }
    }

    for (int t = blockIdx.x; t < ntiles; t += GRID_GEMM) {
        int row0 = t * TILE_M;
        __syncthreads();                 // prev-iter D reads done / B+krel ready

        // ---- store prefetched A regs -> smem as bf16 hi/lo ----
#pragma unroll
        for (int it = 0; it < 8; ++it) {
            int idx = it * 256 + tid;
            int r = idx >> 5, s = idx & 31;
            float4 v = pre[it];
            __nv_bfloat16 h0 = __float2bfloat16_rn(v.x);
            __nv_bfloat16 h1 = __float2bfloat16_rn(v.y);
            __nv_bfloat16 h2 = __float2bfloat16_rn(v.z);
            __nv_bfloat16 h3 = __float2bfloat16_rn(v.w);
            __nv_bfloat162 ph0 = __halves2bfloat162(h0, h1);
            __nv_bfloat162 ph1 = __halves2bfloat162(h2, h3);
            uint2 uh; uh.x = *(uint32_t*)&ph0; uh.y = *(uint32_t*)&ph1;
            *(uint2*)(Ahi + r * K_PAD + 4 * s) = uh;
            __nv_bfloat162 pl0 = __halves2bfloat162(
                __float2bfloat16_rn(v.x - __bfloat162float(h0)),
                __float2bfloat16_rn(v.y - __bfloat162float(h1)));
            __nv_bfloat162 pl1 = __halves2bfloat162(
                __float2bfloat16_rn(v.z - __bfloat162float(h2)),
                __float2bfloat16_rn(v.w - __bfloat162float(h3)));
            uint2 ul; ul.x = *(uint32_t*)&pl0; ul.y = *(uint32_t*)&pl1;
            *(uint2*)(Alo + r * K_PAD + 4 * s) = ul;
        }
        __syncthreads();

        // ---- prefetch NEXT tile's A rows (overlaps with MMA below) ----
        {
            int tn = t + GRID_GEMM;
            int nrow0 = tn * TILE_M;
#pragma unroll
            for (int it = 0; it < 8; ++it) {
                int idx = it * 256 + tid;
                int r = idx >> 5, s = idx & 31;
                int row = nrow0 + r;
                pre[it] = make_float4(0.f, 0.f, 0.f, 0.f);
                if (tn < ntiles && row < n) pre[it] = X4[(size_t)row * 32 + s];
            }
        }

        // ---- 3-pass warp MMA: AhBh + AhBl + AlBh ----
        float acc[2][4][4];              // [m16-tile][n8-tile][frag]
#pragma unroll
        for (int i = 0; i < 2; i++)
#pragma unroll
            for (int j = 0; j < 4; j++)
#pragma unroll
                for (int q = 0; q < 4; q++) acc[i][j][q] = 0.f;

#pragma unroll
        for (int pass = 0; pass < 3; pass++) {
            uint32_t abase = sb + ((pass == 2) ? SM_ALO : SM_A);
            uint32_t bbase = sb + ((pass == 1) ? SM_BLO : SM_BHI);
            uint32_t arow = abase + (uint32_t)(wm * 32) * (K_PAD * 2) + a_loff;
            uint32_t brow = bbase + (uint32_t)(wn * 32) * (K_PAD * 2) + b_loff;
#pragma unroll
            for (int ks = 0; ks < 8; ks++) {
                uint32_t k0 = ks * 32;   // 16 bf16 = 32 bytes
                uint32_t af[2][4], bf[2][4];
#pragma unroll
                for (int mt = 0; mt < 2; mt++)
                    LDMX4(af[mt][0], af[mt][1], af[mt][2], af[mt][3],
                          arow + (uint32_t)(mt * 16) * (K_PAD * 2) + k0);
#pragma unroll
                for (int nt = 0; nt < 2; nt++)
                    LDMX4(bf[nt][0], bf[nt][1], bf[nt][2], bf[nt][3],
                          brow + (uint32_t)(nt * 16) * (K_PAD * 2) + k0);
#pragma unroll
                for (int mt = 0; mt < 2; mt++)
#pragma unroll
                    for (int q = 0; q < 4; q++)
                        mma16816(acc[mt][q], af[mt][0], af[mt][1], af[mt][2], af[mt][3],
                                 bf[q >> 1][(q & 1) * 2], bf[q >> 1][(q & 1) * 2 + 1]);
            }
        }
        __syncthreads();                 // all ldmatrix reads done before D overwrite

        // ---- frags -> D smem (row pad 132) ----
#pragma unroll
        for (int mt = 0; mt < 2; mt++) {
            int row = wm * 32 + mt * 16 + (l >> 2);
#pragma unroll
            for (int q = 0; q < 4; q++) {
                int col = wn * 32 + q * 8 + 2 * (l & 3);
                *(float2*)(D + row * D_PAD + col) = make_float2(acc[mt][q][0], acc[mt][q][1]);
                *(float2*)(D + (row + 8) * D_PAD + col) = make_float2(acc[mt][q][2], acc[mt][q][3]);
            }
        }
        __syncthreads();

        // ---- epilogue ----
        if (MODE == 0) {
#pragma unroll
            for (int it = 0; it < 8; ++it) {
                int idx = it * 256 + tid;    // 2048 float4s
                int r = idx >> 5, s = idx & 31;
                int row = row0 + r;
                if (row < n) {
                    float4 v = *(float4*)(D + r * D_PAD + 4 * s);
                    *(float4*)(g_h_node + (size_t)row * H + 4 * s) = v;
                }
            }
            if (tid < 128) {
                int r = tid & 63;
                int row = row0 + r;
                if (row < n) {
                    const float* av = (tid < 64) ? a1s : a2s;
                    float p = 0.f;
                    const float* dr = D + r * D_PAD;
#pragma unroll 8
                    for (int c = 0; c < H; c++) p = fmaf(dr[c], av[c], p);
                    if (tid < 64) g_s_src[row] = p; else g_s_dst[row] = p;
                }
            }
        } else {
#pragma unroll
            for (int it = 0; it < 8; ++it) {
                int idx = it * 256 + tid;
                int r = idx >> 5, s = idx & 31;
                int row = row0 + r;
                if (row < n) {
                    float4 v = *(float4*)(D + r * D_PAD + 4 * s);
                    *(float4*)(out + (size_t)row * H + 4 * s) =
                        make_float4(tanhf(v.x), tanhf(v.y), tanhf(v.z), tanhf(v.w));
                }
            }
        }
    }
}

// ====== kgather: score -> top10 -> softmax -> gather-agg -> g_neigh =======
#define G_WARPS 8
__global__ void __launch_bounds__(256) kgather(const int* __restrict__ src,
                                               const int* __restrict__ rid, int n) {
    __shared__ float ats[G_WARPS][16];
    __shared__ int   sks[G_WARPS][16];
    __shared__ int   rks[G_WARPS][16];
    int tid = threadIdx.x;
    int w = tid >> 5, l = tid & 31;
    int node = blockIdx.x * G_WARPS + w;
    if (node >= n) return;

    float sdst = g_s_dst[node];
    int s = src[node * DEG + l];
    int r = rid[node * DEG + l];
    float v = (g_s_src[s] + sdst) + g_s_rel[r];
    float sc = (v >= 0.f) ? v : 0.2f * v;

    int rank = 0;
#pragma unroll
    for (int j = 0; j < DEG; j++) {
        float vj = __shfl_sync(0xffffffffu, sc, j);
        rank += (vj > sc) || (vj == sc && j < l);
    }
    bool sel = (rank < TOPK);

    float m = sel ? sc : __int_as_float(0xff800000);
#pragma unroll
    for (int off = 16; off; off >>= 1) m = fmaxf(m, __shfl_xor_sync(0xffffffffu, m, off));
    float e = sel ? expf(sc - m) : 0.f;
    float z = e;
#pragma unroll
    for (int off = 16; off; off >>= 1) z += __shfl_xor_sync(0xffffffffu, z, off);
    float attn = e / z;

    if (sel) { ats[w][rank] = attn; sks[w][rank] = s; rks[w][rank] = r; }
    __syncwarp();

    float4 acc = make_float4(0.f, 0.f, 0.f, 0.f);
#pragma unroll
    for (int k = 0; k < TOPK; k++) {
        int sk = sks[w][k], rk = rks[w][k];
        float ak = ats[w][k];
        // h_node gather: L2-only (no L1 reuse across 76.8MB working set)
        float4 hn = __ldcg((const float4*)(g_h_node + (size_t)sk * H + 4 * l));
        float4 hr = *(const float4*)(g_h_rel + rk * H + 4 * l);
        acc.x = fmaf(ak, hn.x + hr.x, acc.x);
        acc.y = fmaf(ak, hn.y + hr.y, acc.y);
        acc.z = fmaf(ak, hn.z + hr.z, acc.z);
        acc.w = fmaf(ak, hn.w + hr.w, acc.w);
    }
    *(float4*)(g_neigh + (size_t)node * H + 4 * l) = acc;
}

// ============================== launch =====================================
extern "C" void kernel_launch(void* const* d_in, const int* in_sizes, int n_in,
                              void* d_out, int out_size) {
    const float* ent = (const float*)d_in[0];
    const float* rel = (const float*)d_in[1];
    const float* W   = (const float*)d_in[2];
    const float* W_r = (const float*)d_in[3];
    const float* a   = (const float*)d_in[4];
    const float* nw  = (const float*)d_in[5];
    const int*   src = (const int*)d_in[6];
    const int*   rid = (const int*)d_in[7];
    float* out = (float*)d_out;

    int n    = in_sizes[0] / H;   // 150000
    int nrel = in_sizes[1] / H;   // 500
    int ntiles = (n + TILE_M - 1) / TILE_M;

    cudaFuncSetAttribute(kgemm<0>, cudaFuncAttributeMaxDynamicSharedMemorySize, SM_TOTAL);
    cudaFuncSetAttribute(kgemm<1>, cudaFuncAttributeMaxDynamicSharedMemorySize, SM_TOTAL);

    kprepB<<<(H * H + 255) / 256, 256>>>(W, nw);
    kgemm<0><<<GRID_GEMM, 256, SM_TOTAL>>>(ent, a, rel, W_r, nullptr, n, ntiles, nrel);
    kgather<<<(n + G_WARPS - 1) / G_WARPS, 256>>>(src, rid, n);
    kgemm<1><<<GRID_GEMM, 256, SM_TOTAL>>>(nullptr, a, nullptr, nullptr, out, n, ntiles, nrel);
}